// round 12
// baseline (speedup 1.0000x reference)
#include <cuda_runtime.h>
#include <cuda_bf16.h>
#include <math.h>
#include <stdint.h>

// Problem constants (fixed by setup_inputs)
#define BATCH    2
#define FRAMES   16
#define SPATIAL  1024          // 32*32
#define HIDDEN   1024
#define NHEADS   16
#define HDIM     64
#define SEQLEN   (FRAMES*SPATIAL)          // 16384
#define NTOK     (BATCH*SEQLEN)            // 32768
#define QKVDIM   (3*HIDDEN)                // 3072
#define KD       1024                      // K for both GEMMs

// ---------------------------------------------------------------------------
// Scratch (device globals: allocation-free, graph-capturable)
// ---------------------------------------------------------------------------
__device__ __align__(16) __nv_bfloat16 g_xn_hi [(size_t)NTOK * HIDDEN];
__device__ __align__(16) __nv_bfloat16 g_xn_lo [(size_t)NTOK * HIDDEN];
__device__ __align__(16) float         g_qkv   [(size_t)NTOK * QKVDIM];
__device__ __align__(16) __nv_bfloat16 g_att_hi[(size_t)NTOK * HIDDEN];
__device__ __align__(16) __nv_bfloat16 g_att_lo[(size_t)NTOK * HIDDEN];
__device__ __align__(16) __nv_bfloat16 g_wq_hi [(size_t)QKVDIM * HIDDEN];
__device__ __align__(16) __nv_bfloat16 g_wq_lo [(size_t)QKVDIM * HIDDEN];
__device__ __align__(16) __nv_bfloat16 g_wo_hi [(size_t)HIDDEN * HIDDEN];
__device__ __align__(16) __nv_bfloat16 g_wo_lo [(size_t)HIDDEN * HIDDEN];
__device__ __align__(16) float         g_rope_cos[FRAMES * HDIM];
__device__ __align__(16) float         g_rope_sin[FRAMES * HDIM];

// ---------------------------------------------------------------------------
// Helpers
// ---------------------------------------------------------------------------
__device__ __forceinline__ uint32_t smem_u32(const void* p) {
    uint32_t a;
    asm("{ .reg .u64 t; cvta.to.shared.u64 t, %1; cvt.u32.u64 %0, t; }" : "=r"(a) : "l"(p));
    return a;
}

__device__ __forceinline__ void cp_async16(uint32_t s, const void* g) {
    asm volatile("cp.async.cg.shared.global [%0], [%1], 16;" :: "r"(s), "l"(g));
}

__device__ __forceinline__ uint32_t pack_bf2(float a, float b) {
    __nv_bfloat162 t = __floats2bfloat162_rn(a, b);
    return *reinterpret_cast<uint32_t*>(&t);
}

#define LDM4(r, a) \
    asm volatile("ldmatrix.sync.aligned.m8n8.x4.shared.b16 {%0,%1,%2,%3}, [%4];" \
        : "=r"((r)[0]), "=r"((r)[1]), "=r"((r)[2]), "=r"((r)[3]) : "r"(a))

#define MMA16816(c, A, b0, b1) \
    asm volatile("mma.sync.aligned.m16n8k16.row.col.f32.bf16.bf16.f32 " \
        "{%0,%1,%2,%3}, {%4,%5,%6,%7}, {%8,%9}, {%0,%1,%2,%3};" \
        : "+f"((c)[0]), "+f"((c)[1]), "+f"((c)[2]), "+f"((c)[3]) \
        : "r"((A)[0]), "r"((A)[1]), "r"((A)[2]), "r"((A)[3]), "r"(b0), "r"(b1))

// ---------------------------------------------------------------------------
// Kernel 0: split weights into bf16 hi/lo, and fill RoPE tables (block 0)
// ---------------------------------------------------------------------------
__global__ void __launch_bounds__(256) prep_w(
    const float4* __restrict__ wq, const float4* __restrict__ wo,
    uint2* __restrict__ qh, uint2* __restrict__ ql,
    uint2* __restrict__ oh, uint2* __restrict__ ol)
{
    const int i = blockIdx.x * 256 + threadIdx.x;     // 786432 float4s for w_qkv
    float4 w = wq[i];
    float hx = __bfloat162float(__float2bfloat16_rn(w.x));
    float hy = __bfloat162float(__float2bfloat16_rn(w.y));
    float hz = __bfloat162float(__float2bfloat16_rn(w.z));
    float hw = __bfloat162float(__float2bfloat16_rn(w.w));
    qh[i] = make_uint2(pack_bf2(w.x, w.y), pack_bf2(w.z, w.w));
    ql[i] = make_uint2(pack_bf2(w.x - hx, w.y - hy), pack_bf2(w.z - hz, w.w - hw));
    if (i < (HIDDEN * HIDDEN) / 4) {
        float4 v = wo[i];
        float vx = __bfloat162float(__float2bfloat16_rn(v.x));
        float vy = __bfloat162float(__float2bfloat16_rn(v.y));
        float vz = __bfloat162float(__float2bfloat16_rn(v.z));
        float vw = __bfloat162float(__float2bfloat16_rn(v.w));
        oh[i] = make_uint2(pack_bf2(v.x, v.y), pack_bf2(v.z, v.w));
        ol[i] = make_uint2(pack_bf2(v.x - vx, v.y - vy), pack_bf2(v.z - vz, v.w - vw));
    }
    if (blockIdx.x == 0) {
#pragma unroll
        for (int q = 0; q < 4; q++) {
            const int e = threadIdx.x + q * 256;       // 0..1023
            const int t = e >> 6, d = e & 63;
            const float ang = (float)t * expf(-(float)(d & 31) * (9.210340371976184f / 32.0f));
            float sn, cs;
            sincosf(ang, &sn, &cs);
            g_rope_cos[e] = cs;
            g_rope_sin[e] = sn;
        }
    }
}

// ---------------------------------------------------------------------------
// Kernel 1: LayerNorm + temporal transpose, emitting bf16 hi/lo split
// ---------------------------------------------------------------------------
__inline__ __device__ float warpReduceSum(float v) {
#pragma unroll
    for (int o = 16; o > 0; o >>= 1) v += __shfl_down_sync(0xffffffffu, v, o);
    return v;
}

__global__ void __launch_bounds__(256) ln_kernel(
    const float* __restrict__ x,
    const float* __restrict__ gamma,
    const float* __restrict__ beta,
    __nv_bfloat16* __restrict__ xn_hi,
    __nv_bfloat16* __restrict__ xn_lo)
{
    const int token = blockIdx.x;
    const float4* row = (const float4*)(x + (size_t)token * HIDDEN);
    float4 v = row[threadIdx.x];
    float s  = v.x + v.y + v.z + v.w;
    float ss = v.x*v.x + v.y*v.y + v.z*v.z + v.w*v.w;

    __shared__ float sb[8], ssb[8];
    __shared__ float s_mean, s_inv;
    float ws  = warpReduceSum(s);
    float wss = warpReduceSum(ss);
    const int lane = threadIdx.x & 31, warp = threadIdx.x >> 5;
    if (lane == 0) { sb[warp] = ws; ssb[warp] = wss; }
    __syncthreads();
    if (threadIdx.x == 0) {
        float ts = 0.f, tss = 0.f;
#pragma unroll
        for (int i = 0; i < 8; i++) { ts += sb[i]; tss += ssb[i]; }
        float mean = ts * (1.0f / HIDDEN);
        float var  = tss * (1.0f / HIDDEN) - mean * mean;
        s_mean = mean;
        s_inv  = rsqrtf(var + 1e-5f);
    }
    __syncthreads();
    const float mean = s_mean, inv = s_inv;

    float4 g4 = ((const float4*)gamma)[threadIdx.x];
    float4 b4 = ((const float4*)beta )[threadIdx.x];
    float4 o;
    o.x = (v.x - mean) * inv * g4.x + b4.x;
    o.y = (v.y - mean) * inv * g4.y + b4.y;
    o.z = (v.z - mean) * inv * g4.z + b4.z;
    o.w = (v.w - mean) * inv * g4.w + b4.w;

    float hx = __bfloat162float(__float2bfloat16_rn(o.x));
    float hy = __bfloat162float(__float2bfloat16_rn(o.y));
    float hz = __bfloat162float(__float2bfloat16_rn(o.z));
    float hw = __bfloat162float(__float2bfloat16_rn(o.w));

    const int b  = token >> 14;
    const int rm = token & 16383;
    const int t  = rm >> 10;
    const int sp = rm & 1023;
    const int r  = b * 16384 + sp * 16 + t;
    ((uint2*)(xn_hi + (size_t)r * HIDDEN))[threadIdx.x] =
        make_uint2(pack_bf2(o.x, o.y), pack_bf2(o.z, o.w));
    ((uint2*)(xn_lo + (size_t)r * HIDDEN))[threadIdx.x] =
        make_uint2(pack_bf2(o.x - hx, o.y - hy), pack_bf2(o.z - hz, o.w - hw));
}

// ---------------------------------------------------------------------------
// Kernel 2/4: bf16x3 error-compensated NT GEMM via mma.sync (HMMA path).
//   C[M,N] = (Ah+Al)[M,K] * (Bh+Bl)[N,K]^T ~= Ah*Bh + Al*Bh + Ah*Bl
//   128x128 CTA tile, BK=32, 3-stage cp.async pipeline (96KB -> 2 CTA/SM),
//   256 threads = 8 warps (4 m x 2 n), warp tile 32x64, fp32 accum.
//   SMEM rows are 64B (32 bf16); swizzle: chunk' = ch ^ ((row>>1)&3)
//   -> conflict-free for both cp.async stores and ldmatrix 8-row phases.
// ---------------------------------------------------------------------------
#define BK      32
#define STG     3
#define TILE_B  (128 * BK * 2)             // 8192 B: one 128x32 bf16 tile
#define STAGE_B (4 * TILE_B)               // Ah | Al | Bh | Bl = 32768 B
#define SMEM_GEMM (STG * STAGE_B)          // 98304
#define NITER   (KD / BK)                  // 32

__global__ void __launch_bounds__(256, 2) gemm_bf16x3(
    const __nv_bfloat16* __restrict__ Ah, const __nv_bfloat16* __restrict__ Al,
    const __nv_bfloat16* __restrict__ Bh, const __nv_bfloat16* __restrict__ Bl,
    float* __restrict__ C, int N)
{
    extern __shared__ char smem[];
    const uint32_t sb = smem_u32(smem);

    const int tid  = threadIdx.x;
    const int lane = tid & 31;
    const int w    = tid >> 5;
    const int wm   = w & 3;          // 4 m-warps (32 rows each)
    const int wn   = w >> 2;         // 2 n-warps (64 cols each)

    const __nv_bfloat16* aTh = Ah + (size_t)blockIdx.y * 128 * KD;
    const __nv_bfloat16* aTl = Al + (size_t)blockIdx.y * 128 * KD;
    const __nv_bfloat16* bTh = Bh + (size_t)blockIdx.x * 128 * KD;
    const __nv_bfloat16* bTl = Bl + (size_t)blockIdx.x * 128 * KD;

    // ldmatrix lane-address precompute
    const int csel = lane >> 4;                 // +0 / +1 16B chunk within k16
    uint32_t aBase[2]; int swA[2];
#pragma unroll
    for (int mt = 0; mt < 2; mt++) {
        int row = wm * 32 + mt * 16 + (lane & 15);
        aBase[mt] = (uint32_t)row * 64; swA[mt] = (row >> 1) & 3;
    }
    uint32_t bBase[4]; int swB[4];
#pragma unroll
    for (int pt = 0; pt < 4; pt++) {
        int row = wn * 64 + pt * 16 + (lane & 15);
        bBase[pt] = (uint32_t)row * 64; swB[pt] = (row >> 1) & 3;
    }

    float acc[2][8][4];
#pragma unroll
    for (int i = 0; i < 2; i++)
#pragma unroll
        for (int j = 0; j < 8; j++)
#pragma unroll
            for (int q = 0; q < 4; q++) acc[i][j][q] = 0.f;

    // stage loader: 4 matrices x 512 16B-chunks, 8 cp.async per thread
    auto load_stage = [&](int s, int k0) {
        const uint32_t st = sb + (uint32_t)s * STAGE_B;
#pragma unroll
        for (int i = 0; i < 2; i++) {
            const int cidx = tid + i * 256;          // 0..511
            const int r = cidx >> 2, ch = cidx & 3;
            const uint32_t so = (uint32_t)r * 64 + ((ch ^ ((r >> 1) & 3)) << 4);
            const size_t go = (size_t)r * KD + k0 + ch * 8;
            cp_async16(st + 0*TILE_B + so, aTh + go);
            cp_async16(st + 1*TILE_B + so, aTl + go);
            cp_async16(st + 2*TILE_B + so, bTh + go);
            cp_async16(st + 3*TILE_B + so, bTl + go);
        }
    };

    // prologue: stages 0,1
    load_stage(0, 0);
    asm volatile("cp.async.commit_group;" ::: "memory");
    load_stage(1, BK);
    asm volatile("cp.async.commit_group;" ::: "memory");

    for (int it = 0; it < NITER; ++it) {
        if (it + 2 < NITER) load_stage((it + 2) % STG, (it + 2) * BK);
        asm volatile("cp.async.commit_group;" ::: "memory");
        asm volatile("cp.async.wait_group %0;" :: "n"(STG - 1));
        __syncthreads();

        const uint32_t st = sb + (uint32_t)(it % STG) * STAGE_B;
#pragma unroll
        for (int ks = 0; ks < 2; ks++) {
            const int kc = ks * 2;
            uint32_t ah[2][4], al[2][4];
#pragma unroll
            for (int mt = 0; mt < 2; mt++) {
                const uint32_t ad = st + aBase[mt] + (((kc + csel) ^ swA[mt]) << 4);
                LDM4(ah[mt], ad);
                LDM4(al[mt], ad + TILE_B);
            }
#pragma unroll
            for (int pt = 0; pt < 4; pt++) {
                uint32_t bh[4], bl[4];
                const uint32_t bd = st + 2*TILE_B + bBase[pt] + (((kc + csel) ^ swB[pt]) << 4);
                LDM4(bh, bd);
                LDM4(bl, bd + TILE_B);
#pragma unroll
                for (int mt = 0; mt < 2; mt++)
#pragma unroll
                    for (int hf = 0; hf < 2; hf++) {
                        float* c = acc[mt][pt * 2 + hf];
                        MMA16816(c, ah[mt], bh[hf], bh[2 + hf]);
                        MMA16816(c, al[mt], bh[hf], bh[2 + hf]);
                        MMA16816(c, ah[mt], bl[hf], bl[2 + hf]);
                    }
            }
        }
        __syncthreads();
    }

    // epilogue: direct fp32 stores
#pragma unroll
    for (int mt = 0; mt < 2; mt++) {
        const int row = blockIdx.y * 128 + wm * 32 + mt * 16 + (lane >> 2);
#pragma unroll
        for (int nt = 0; nt < 8; nt++) {
            const int col = blockIdx.x * 128 + wn * 64 + nt * 8 + 2 * (lane & 3);
            float* p = C + (size_t)row * N + col;
            *(float2*)p                   = make_float2(acc[mt][nt][0], acc[mt][nt][1]);
            *(float2*)(p + 8 * (size_t)N) = make_float2(acc[mt][nt][2], acc[mt][nt][3]);
        }
    }
}

// ---------------------------------------------------------------------------
// Kernel 3: per-(n,h) RoPE + causal attention, table-based, vectorized I/O,
// emits bf16 hi/lo split output.
// ---------------------------------------------------------------------------
__global__ void __launch_bounds__(128) attn_kernel(
    const float* __restrict__ qkv,
    __nv_bfloat16* __restrict__ att_hi,
    __nv_bfloat16* __restrict__ att_lo)
{
    __shared__ float rawq[16*64], rawk[16*64];
    __shared__ float qr[16*64], kr[16*64], vs[16*64];
    __shared__ float p[16][17];

    const int nh = blockIdx.x;
    const int n  = nh >> 4;
    const int hh = nh & 15;
    const int tid = threadIdx.x;

    const float* base = qkv + (size_t)n * FRAMES * QKVDIM + hh * HDIM;

    // vectorized loads: 256 float4 per matrix, 2 per thread
#pragma unroll
    for (int i = tid; i < 256; i += 128) {
        const int t = i >> 4, f = i & 15;
        const float4* rp = (const float4*)(base + (size_t)t * QKVDIM);
        ((float4*)rawq)[i] = rp[f];
        ((float4*)rawk)[i] = rp[256 + f];      // +HIDDEN floats = +256 float4
        ((float4*)vs)[i]   = rp[512 + f];      // +2*HIDDEN
    }
    __syncthreads();

    // RoPE from precomputed tables
#pragma unroll
    for (int i = tid; i < FRAMES * HDIM; i += 128) {
        const int d = i & 63;
        const float cs = g_rope_cos[i], sn = g_rope_sin[i];
        const int pi = (d < 32) ? i + 32 : i - 32;
        const float rq = (d < 32) ? -rawq[pi] : rawq[pi];
        const float rk = (d < 32) ? -rawk[pi] : rawk[pi];
        qr[i] = rawq[i] * cs + rq * sn;
        kr[i] = rawk[i] * cs + rk * sn;
    }
    __syncthreads();

    // scores (causal), scale = 0.125
#pragma unroll
    for (int e = tid; e < 256; e += 128) {
        const int qi = e >> 4, kj = e & 15;
        float sc;
        if (kj > qi) sc = -INFINITY;
        else {
            float dsum = 0.f;
#pragma unroll
            for (int d = 0; d < 64; d++) dsum = fmaf(qr[qi*64+d], kr[kj*64+d], dsum);
            sc = dsum * 0.125f;
        }
        p[qi][kj] = sc;
    }
    __syncthreads();

    if (tid < 16) {
        float mx = -INFINITY;
#pragma unroll
        for (int j = 0; j < 16; j++) mx = fmaxf(mx, p[tid][j]);
        float sum = 0.f;
#pragma unroll
        for (int j = 0; j < 16; j++) {
            float e2 = (j <= tid) ? expf(p[tid][j] - mx) : 0.f;
            p[tid][j] = e2;
            sum += e2;
        }
        const float isum = 1.0f / sum;
#pragma unroll
        for (int j = 0; j < 16; j++) p[tid][j] *= isum;
    }
    __syncthreads();

    // out = attn @ v; packed bf16x2 stores of hi and lo
    const int b = n >> 10, sp = n & 1023;
#pragma unroll
    for (int i = tid; i < 512; i += 128) {
        const int t = i >> 5, dp = i & 31;     // d = 2*dp
        float o0 = 0.f, o1 = 0.f;
#pragma unroll
        for (int k = 0; k < 16; k++) {
            const float w = p[t][k];
            o0 = fmaf(w, vs[k*64 + 2*dp],     o0);
            o1 = fmaf(w, vs[k*64 + 2*dp + 1], o1);
        }
        const size_t idx = (size_t)(b * SEQLEN + t * SPATIAL + sp) * HIDDEN + hh * HDIM + 2 * dp;
        const float h0 = __bfloat162float(__float2bfloat16_rn(o0));
        const float h1 = __bfloat162float(__float2bfloat16_rn(o1));
        *(uint32_t*)(att_hi + idx) = pack_bf2(o0, o1);
        *(uint32_t*)(att_lo + idx) = pack_bf2(o0 - h0, o1 - h1);
    }
}

// ---------------------------------------------------------------------------
extern "C" void kernel_launch(void* const* d_in, const int* in_sizes, int n_in,
                              void* d_out, int out_size)
{
    const float* x      = (const float*)d_in[0];
    const float* w_qkv  = (const float*)d_in[1];
    const float* w_out  = (const float*)d_in[2];
    const float* gamma  = (const float*)d_in[3];
    const float* beta   = (const float*)d_in[4];
    float* out = (float*)d_out;

    __nv_bfloat16 *xnh, *xnl, *ath, *atl, *wqh, *wql, *woh, *wol;
    float *qkv;
    cudaGetSymbolAddress((void**)&xnh, g_xn_hi);
    cudaGetSymbolAddress((void**)&xnl, g_xn_lo);
    cudaGetSymbolAddress((void**)&qkv, g_qkv);
    cudaGetSymbolAddress((void**)&ath, g_att_hi);
    cudaGetSymbolAddress((void**)&atl, g_att_lo);
    cudaGetSymbolAddress((void**)&wqh, g_wq_hi);
    cudaGetSymbolAddress((void**)&wql, g_wq_lo);
    cudaGetSymbolAddress((void**)&woh, g_wo_hi);
    cudaGetSymbolAddress((void**)&wol, g_wo_lo);

    cudaFuncSetAttribute(gemm_bf16x3, cudaFuncAttributeMaxDynamicSharedMemorySize, SMEM_GEMM);

    // 0) Split weights into bf16 hi/lo + RoPE tables
    prep_w<<<(QKVDIM * HIDDEN / 4) / 256, 256>>>(
        (const float4*)w_qkv, (const float4*)w_out,
        (uint2*)wqh, (uint2*)wql, (uint2*)woh, (uint2*)wol);

    // 1) LayerNorm + temporal transpose (bf16 split output)
    ln_kernel<<<NTOK, 256>>>(x, gamma, beta, xnh, xnl);

    // 2) QKV GEMM: [32768,1024] x [3072,1024]^T -> [32768,3072] fp32
    gemm_bf16x3<<<dim3(QKVDIM / 128, NTOK / 128), 256, SMEM_GEMM>>>(
        xnh, xnl, wqh, wql, qkv, QKVDIM);

    // 3) RoPE + causal attention per (n, h), bf16 split output
    attn_kernel<<<BATCH * SPATIAL * NHEADS, 128>>>(qkv, ath, atl);

    // 4) Output projection: [32768,1024] x [1024,1024]^T -> d_out fp32
    gemm_bf16x3<<<dim3(HIDDEN / 128, NTOK / 128), 256, SMEM_GEMM>>>(
        ath, atl, woh, wol, out, HIDDEN);
}

// round 14
// speedup vs baseline: 1.5109x; 1.5109x over previous
#include <cuda_runtime.h>
#include <cuda_bf16.h>
#include <math.h>
#include <stdint.h>

// Problem constants (fixed by setup_inputs)
#define BATCH    2
#define FRAMES   16
#define SPATIAL  1024          // 32*32
#define HIDDEN   1024
#define NHEADS   16
#define HDIM     64
#define SEQLEN   (FRAMES*SPATIAL)          // 16384
#define NTOK     (BATCH*SEQLEN)            // 32768
#define QKVDIM   (3*HIDDEN)                // 3072
#define KD       1024                      // K for both GEMMs

// ---------------------------------------------------------------------------
// Scratch (device globals: allocation-free, graph-capturable)
// ---------------------------------------------------------------------------
__device__ __align__(16) __nv_bfloat16 g_xn_hi [(size_t)NTOK * HIDDEN];
__device__ __align__(16) __nv_bfloat16 g_xn_lo [(size_t)NTOK * HIDDEN];
__device__ __align__(16) float         g_qkv   [(size_t)NTOK * QKVDIM];
__device__ __align__(16) __nv_bfloat16 g_att_hi[(size_t)NTOK * HIDDEN];
__device__ __align__(16) __nv_bfloat16 g_att_lo[(size_t)NTOK * HIDDEN];
__device__ __align__(16) __nv_bfloat16 g_wq_hi [(size_t)QKVDIM * HIDDEN];
__device__ __align__(16) __nv_bfloat16 g_wq_lo [(size_t)QKVDIM * HIDDEN];
__device__ __align__(16) __nv_bfloat16 g_wo_hi [(size_t)HIDDEN * HIDDEN];
__device__ __align__(16) __nv_bfloat16 g_wo_lo [(size_t)HIDDEN * HIDDEN];

// ---------------------------------------------------------------------------
// Helpers
// ---------------------------------------------------------------------------
__device__ __forceinline__ uint32_t smem_u32(const void* p) {
    uint32_t a;
    asm("{ .reg .u64 t; cvta.to.shared.u64 t, %1; cvt.u32.u64 %0, t; }" : "=r"(a) : "l"(p));
    return a;
}

__device__ __forceinline__ void cp_async16(uint32_t s, const void* g) {
    asm volatile("cp.async.cg.shared.global [%0], [%1], 16;" :: "r"(s), "l"(g));
}

__device__ __forceinline__ uint32_t pack_bf2(float a, float b) {
    __nv_bfloat162 t = __floats2bfloat162_rn(a, b);
    return *reinterpret_cast<uint32_t*>(&t);
}

#define LDM4(r, a) \
    asm volatile("ldmatrix.sync.aligned.m8n8.x4.shared.b16 {%0,%1,%2,%3}, [%4];" \
        : "=r"((r)[0]), "=r"((r)[1]), "=r"((r)[2]), "=r"((r)[3]) : "r"(a))

#define MMA16816(c, A, b0, b1) \
    asm volatile("mma.sync.aligned.m16n8k16.row.col.f32.bf16.bf16.f32 " \
        "{%0,%1,%2,%3}, {%4,%5,%6,%7}, {%8,%9}, {%0,%1,%2,%3};" \
        : "+f"((c)[0]), "+f"((c)[1]), "+f"((c)[2]), "+f"((c)[3]) \
        : "r"((A)[0]), "r"((A)[1]), "r"((A)[2]), "r"((A)[3]), "r"(b0), "r"(b1))

// ---------------------------------------------------------------------------
// Kernel 0: split weights into bf16 hi/lo
// ---------------------------------------------------------------------------
__global__ void __launch_bounds__(256) prep_w(
    const float4* __restrict__ wq, const float4* __restrict__ wo,
    uint2* __restrict__ qh, uint2* __restrict__ ql,
    uint2* __restrict__ oh, uint2* __restrict__ ol)
{
    const int i = blockIdx.x * 256 + threadIdx.x;     // 786432 float4s for w_qkv
    float4 w = wq[i];
    float hx = __bfloat162float(__float2bfloat16_rn(w.x));
    float hy = __bfloat162float(__float2bfloat16_rn(w.y));
    float hz = __bfloat162float(__float2bfloat16_rn(w.z));
    float hw = __bfloat162float(__float2bfloat16_rn(w.w));
    qh[i] = make_uint2(pack_bf2(w.x, w.y), pack_bf2(w.z, w.w));
    ql[i] = make_uint2(pack_bf2(w.x - hx, w.y - hy), pack_bf2(w.z - hz, w.w - hw));
    if (i < (HIDDEN * HIDDEN) / 4) {
        float4 v = wo[i];
        float vx = __bfloat162float(__float2bfloat16_rn(v.x));
        float vy = __bfloat162float(__float2bfloat16_rn(v.y));
        float vz = __bfloat162float(__float2bfloat16_rn(v.z));
        float vw = __bfloat162float(__float2bfloat16_rn(v.w));
        oh[i] = make_uint2(pack_bf2(v.x, v.y), pack_bf2(v.z, v.w));
        ol[i] = make_uint2(pack_bf2(v.x - vx, v.y - vy), pack_bf2(v.z - vz, v.w - vw));
    }
}

// ---------------------------------------------------------------------------
// Kernel 1: LayerNorm + temporal transpose, emitting bf16 hi/lo split
// ---------------------------------------------------------------------------
__inline__ __device__ float warpReduceSum(float v) {
#pragma unroll
    for (int o = 16; o > 0; o >>= 1) v += __shfl_down_sync(0xffffffffu, v, o);
    return v;
}

__global__ void __launch_bounds__(256) ln_kernel(
    const float* __restrict__ x,
    const float* __restrict__ gamma,
    const float* __restrict__ beta,
    __nv_bfloat16* __restrict__ xn_hi,
    __nv_bfloat16* __restrict__ xn_lo)
{
    const int token = blockIdx.x;
    const float4* row = (const float4*)(x + (size_t)token * HIDDEN);
    float4 v = row[threadIdx.x];
    float s  = v.x + v.y + v.z + v.w;
    float ss = v.x*v.x + v.y*v.y + v.z*v.z + v.w*v.w;

    __shared__ float sb[8], ssb[8];
    __shared__ float s_mean, s_inv;
    float ws  = warpReduceSum(s);
    float wss = warpReduceSum(ss);
    const int lane = threadIdx.x & 31, warp = threadIdx.x >> 5;
    if (lane == 0) { sb[warp] = ws; ssb[warp] = wss; }
    __syncthreads();
    if (threadIdx.x == 0) {
        float ts = 0.f, tss = 0.f;
#pragma unroll
        for (int i = 0; i < 8; i++) { ts += sb[i]; tss += ssb[i]; }
        float mean = ts * (1.0f / HIDDEN);
        float var  = tss * (1.0f / HIDDEN) - mean * mean;
        s_mean = mean;
        s_inv  = rsqrtf(var + 1e-5f);
    }
    __syncthreads();
    const float mean = s_mean, inv = s_inv;

    float4 g4 = ((const float4*)gamma)[threadIdx.x];
    float4 b4 = ((const float4*)beta )[threadIdx.x];
    float4 o;
    o.x = (v.x - mean) * inv * g4.x + b4.x;
    o.y = (v.y - mean) * inv * g4.y + b4.y;
    o.z = (v.z - mean) * inv * g4.z + b4.z;
    o.w = (v.w - mean) * inv * g4.w + b4.w;

    float hx = __bfloat162float(__float2bfloat16_rn(o.x));
    float hy = __bfloat162float(__float2bfloat16_rn(o.y));
    float hz = __bfloat162float(__float2bfloat16_rn(o.z));
    float hw = __bfloat162float(__float2bfloat16_rn(o.w));

    const int b  = token >> 14;
    const int rm = token & 16383;
    const int t  = rm >> 10;
    const int sp = rm & 1023;
    const int r  = b * 16384 + sp * 16 + t;
    ((uint2*)(xn_hi + (size_t)r * HIDDEN))[threadIdx.x] =
        make_uint2(pack_bf2(o.x, o.y), pack_bf2(o.z, o.w));
    ((uint2*)(xn_lo + (size_t)r * HIDDEN))[threadIdx.x] =
        make_uint2(pack_bf2(o.x - hx, o.y - hy), pack_bf2(o.z - hz, o.w - hw));
}

// ---------------------------------------------------------------------------
// Kernel 2/4: bf16x3 error-compensated NT GEMM via mma.sync (HMMA path).
//   C[M,N] = (Ah+Al)[M,K] * (Bh+Bl)[N,K]^T ~= Ah*Bh + Al*Bh + Ah*Bl
//   128x128 CTA tile, BK=64, 3-stage cp.async pipeline, SW128 swizzle,
//   256 threads = 8 warps (4 m x 2 n), warp tile 32x64, fp32 accum.
//   (R11 configuration — known good at 2637us total.)
// ---------------------------------------------------------------------------
#define BK      64
#define STG     3
#define TILE_B  16384                      // one 128x64 bf16 tile
#define STAGE_B (4 * TILE_B)               // Ah | Al | Bh | Bl
#define SMEM_GEMM (STG * STAGE_B)          // 196608
#define NITER   (KD / BK)                  // 16

__global__ void __launch_bounds__(256, 1) gemm_bf16x3(
    const __nv_bfloat16* __restrict__ Ah, const __nv_bfloat16* __restrict__ Al,
    const __nv_bfloat16* __restrict__ Bh, const __nv_bfloat16* __restrict__ Bl,
    float* __restrict__ C, int N)
{
    extern __shared__ char smem[];
    const uint32_t sb = smem_u32(smem);

    const int tid  = threadIdx.x;
    const int lane = tid & 31;
    const int w    = tid >> 5;
    const int wm   = w & 3;          // 4 m-warps (32 rows each)
    const int wn   = w >> 2;         // 2 n-warps (64 cols each)

    const __nv_bfloat16* aTh = Ah + (size_t)blockIdx.y * 128 * KD;
    const __nv_bfloat16* aTl = Al + (size_t)blockIdx.y * 128 * KD;
    const __nv_bfloat16* bTh = Bh + (size_t)blockIdx.x * 128 * KD;
    const __nv_bfloat16* bTl = Bl + (size_t)blockIdx.x * 128 * KD;

    // ldmatrix lane-address precompute (SW128: chunk' = chunk ^ (row & 7))
    const int csel = lane >> 4;                 // +0 / +1 chunk (k0 / k0+8)
    uint32_t aBase[2]; int swA[2];
#pragma unroll
    for (int mt = 0; mt < 2; mt++) {
        int row = wm * 32 + mt * 16 + (lane & 15);
        aBase[mt] = (uint32_t)row * 128; swA[mt] = row & 7;
    }
    uint32_t bBase[4]; int swB[4];
#pragma unroll
    for (int pt = 0; pt < 4; pt++) {
        int row = wn * 64 + pt * 16 + (lane & 15);
        bBase[pt] = (uint32_t)row * 128; swB[pt] = row & 7;
    }

    float acc[2][8][4];
#pragma unroll
    for (int i = 0; i < 2; i++)
#pragma unroll
        for (int j = 0; j < 8; j++)
#pragma unroll
            for (int q = 0; q < 4; q++) acc[i][j][q] = 0.f;

    // stage loader: 4 matrices x 1024 16B-chunks, 16 cp.async per thread
    auto load_stage = [&](int s, int k0) {
        const uint32_t st = sb + (uint32_t)s * STAGE_B;
#pragma unroll
        for (int i = 0; i < 4; i++) {
            const int cidx = tid + i * 256;          // 0..1023
            const int r = cidx >> 3, ch = cidx & 7;
            const uint32_t so = (uint32_t)r * 128 + ((ch ^ (r & 7)) << 4);
            const size_t go = (size_t)r * KD + k0 + ch * 8;
            cp_async16(st + 0*TILE_B + so, aTh + go);
            cp_async16(st + 1*TILE_B + so, aTl + go);
            cp_async16(st + 2*TILE_B + so, bTh + go);
            cp_async16(st + 3*TILE_B + so, bTl + go);
        }
    };

    // prologue: stages 0,1
    load_stage(0, 0);
    asm volatile("cp.async.commit_group;" ::: "memory");
    load_stage(1, BK);
    asm volatile("cp.async.commit_group;" ::: "memory");

    for (int it = 0; it < NITER; ++it) {
        if (it + 2 < NITER) load_stage((it + 2) % STG, (it + 2) * BK);
        asm volatile("cp.async.commit_group;" ::: "memory");
        asm volatile("cp.async.wait_group %0;" :: "n"(STG - 1));
        __syncthreads();

        const uint32_t st = sb + (uint32_t)(it % STG) * STAGE_B;
#pragma unroll
        for (int ks = 0; ks < 4; ks++) {
            const int kc = ks * 2;
            uint32_t ah[2][4], al[2][4];
#pragma unroll
            for (int mt = 0; mt < 2; mt++) {
                const uint32_t ad = st + aBase[mt] + (((kc + csel) ^ swA[mt]) << 4);
                LDM4(ah[mt], ad);
                LDM4(al[mt], ad + TILE_B);
            }
            uint32_t bh[4][4], bl[4][4];
#pragma unroll
            for (int pt = 0; pt < 4; pt++) {
                const uint32_t bd = st + 2*TILE_B + bBase[pt] + (((kc + csel) ^ swB[pt]) << 4);
                LDM4(bh[pt], bd);
                LDM4(bl[pt], bd + TILE_B);
            }
#pragma unroll
            for (int mt = 0; mt < 2; mt++)
#pragma unroll
                for (int nt = 0; nt < 8; nt++) {
                    const int pt = nt >> 1, hf = nt & 1;
                    MMA16816(acc[mt][nt], ah[mt], bh[pt][hf], bh[pt][2 + hf]);
                    MMA16816(acc[mt][nt], al[mt], bh[pt][hf], bh[pt][2 + hf]);
                    MMA16816(acc[mt][nt], ah[mt], bl[pt][hf], bl[pt][2 + hf]);
                }
        }
        __syncthreads();
    }

    // epilogue: direct fp32 stores
#pragma unroll
    for (int mt = 0; mt < 2; mt++) {
        const int row = blockIdx.y * 128 + wm * 32 + mt * 16 + (lane >> 2);
#pragma unroll
        for (int nt = 0; nt < 8; nt++) {
            const int col = blockIdx.x * 128 + wn * 64 + nt * 8 + 2 * (lane & 3);
            float* p = C + (size_t)row * N + col;
            *(float2*)p                   = make_float2(acc[mt][nt][0], acc[mt][nt][1]);
            *(float2*)(p + 8 * (size_t)N) = make_float2(acc[mt][nt][2], acc[mt][nt][3]);
        }
    }
}

// ---------------------------------------------------------------------------
// Kernel 3: per-(n,h) RoPE + causal attention.
//   R11 base (in-kernel sincosf RoPE) + float4 q/k/v loads, hoisted expf
//   (d is invariant per thread across its strided elements), packed bf16x2
//   hi/lo stores. No gmem table reads.
// ---------------------------------------------------------------------------
__global__ void __launch_bounds__(128) attn_kernel(
    const float* __restrict__ qkv,
    __nv_bfloat16* __restrict__ att_hi,
    __nv_bfloat16* __restrict__ att_lo)
{
    __shared__ float rawq[16*64], rawk[16*64];
    __shared__ float qr[16*64], kr[16*64], vs[16*64];
    __shared__ float p[16][17];

    const int nh = blockIdx.x;
    const int n  = nh >> 4;
    const int hh = nh & 15;
    const int tid = threadIdx.x;

    const float* base = qkv + (size_t)n * FRAMES * QKVDIM + hh * HDIM;

    // vectorized loads: 256 float4 per matrix, 2 per thread each of q/k/v
#pragma unroll
    for (int i = tid; i < 256; i += 128) {
        const int t = i >> 4, f = i & 15;
        const float4* rp = (const float4*)(base + (size_t)t * QKVDIM);
        ((float4*)rawq)[i] = rp[f];
        ((float4*)rawk)[i] = rp[256 + f];      // +HIDDEN floats
        ((float4*)vs)[i]   = rp[512 + f];      // +2*HIDDEN floats
    }
    __syncthreads();

    // RoPE: d = tid&63 is invariant across this thread's 8 elements -> 1 expf
    {
        const int d = tid & 63;
        const float invf = expf(-(float)(d & 31) * (9.210340371976184f / 32.0f));
        const int pd = (d < 32) ? d + 32 : d - 32;
        const float sgn = (d < 32) ? -1.0f : 1.0f;
#pragma unroll
        for (int i = tid; i < FRAMES * HDIM; i += 128) {
            const int t = i >> 6;
            float sn, cs;
            sincosf((float)t * invf, &sn, &cs);
            const int pi = (i & ~63) + pd;
            qr[i] = rawq[i] * cs + sgn * rawq[pi] * sn;
            kr[i] = rawk[i] * cs + sgn * rawk[pi] * sn;
        }
    }
    __syncthreads();

    // scores (causal), scale = 0.125
#pragma unroll
    for (int e = tid; e < 256; e += 128) {
        const int qi = e >> 4, kj = e & 15;
        float sc;
        if (kj > qi) sc = -INFINITY;
        else {
            float dsum = 0.f;
#pragma unroll
            for (int d = 0; d < 64; d++) dsum = fmaf(qr[qi*64+d], kr[kj*64+d], dsum);
            sc = dsum * 0.125f;
        }
        p[qi][kj] = sc;
    }
    __syncthreads();

    if (tid < 16) {
        float mx = -INFINITY;
#pragma unroll
        for (int j = 0; j < 16; j++) mx = fmaxf(mx, p[tid][j]);
        float sum = 0.f;
#pragma unroll
        for (int j = 0; j < 16; j++) {
            float e2 = (j <= tid) ? expf(p[tid][j] - mx) : 0.f;
            p[tid][j] = e2;
            sum += e2;
        }
        const float isum = 1.0f / sum;
#pragma unroll
        for (int j = 0; j < 16; j++) p[tid][j] *= isum;
    }
    __syncthreads();

    // out = attn @ v; packed bf16x2 stores of hi and lo
    const int b = n >> 10, sp = n & 1023;
#pragma unroll
    for (int i = tid; i < 512; i += 128) {
        const int t = i >> 5, dp = i & 31;     // element pair d = 2*dp
        float o0 = 0.f, o1 = 0.f;
#pragma unroll
        for (int k = 0; k < 16; k++) {
            const float wgt = p[t][k];
            o0 = fmaf(wgt, vs[k*64 + 2*dp],     o0);
            o1 = fmaf(wgt, vs[k*64 + 2*dp + 1], o1);
        }
        const size_t idx = (size_t)(b * SEQLEN + t * SPATIAL + sp) * HIDDEN + hh * HDIM + 2 * dp;
        const float h0 = __bfloat162float(__float2bfloat16_rn(o0));
        const float h1 = __bfloat162float(__float2bfloat16_rn(o1));
        *(uint32_t*)(att_hi + idx) = pack_bf2(o0, o1);
        *(uint32_t*)(att_lo + idx) = pack_bf2(o0 - h0, o1 - h1);
    }
}

// ---------------------------------------------------------------------------
extern "C" void kernel_launch(void* const* d_in, const int* in_sizes, int n_in,
                              void* d_out, int out_size)
{
    const float* x      = (const float*)d_in[0];
    const float* w_qkv  = (const float*)d_in[1];
    const float* w_out  = (const float*)d_in[2];
    const float* gamma  = (const float*)d_in[3];
    const float* beta   = (const float*)d_in[4];
    float* out = (float*)d_out;

    __nv_bfloat16 *xnh, *xnl, *ath, *atl, *wqh, *wql, *woh, *wol;
    float *qkv;
    cudaGetSymbolAddress((void**)&xnh, g_xn_hi);
    cudaGetSymbolAddress((void**)&xnl, g_xn_lo);
    cudaGetSymbolAddress((void**)&qkv, g_qkv);
    cudaGetSymbolAddress((void**)&ath, g_att_hi);
    cudaGetSymbolAddress((void**)&atl, g_att_lo);
    cudaGetSymbolAddress((void**)&wqh, g_wq_hi);
    cudaGetSymbolAddress((void**)&wql, g_wq_lo);
    cudaGetSymbolAddress((void**)&woh, g_wo_hi);
    cudaGetSymbolAddress((void**)&wol, g_wo_lo);

    cudaFuncSetAttribute(gemm_bf16x3, cudaFuncAttributeMaxDynamicSharedMemorySize, SMEM_GEMM);

    // 0) Split weights into bf16 hi/lo
    prep_w<<<(QKVDIM * HIDDEN / 4) / 256, 256>>>(
        (const float4*)w_qkv, (const float4*)w_out,
        (uint2*)wqh, (uint2*)wql, (uint2*)woh, (uint2*)wol);

    // 1) LayerNorm + temporal transpose (bf16 split output)
    ln_kernel<<<NTOK, 256>>>(x, gamma, beta, xnh, xnl);

    // 2) QKV GEMM: [32768,1024] x [3072,1024]^T -> [32768,3072] fp32
    gemm_bf16x3<<<dim3(QKVDIM / 128, NTOK / 128), 256, SMEM_GEMM>>>(
        xnh, xnl, wqh, wql, qkv, QKVDIM);

    // 3) RoPE + causal attention per (n, h), bf16 split output
    attn_kernel<<<BATCH * SPATIAL * NHEADS, 128>>>(qkv, ath, atl);

    // 4) Output projection: [32768,1024] x [1024,1024]^T -> d_out fp32
    gemm_bf16x3<<<dim3(HIDDEN / 128, NTOK / 128), 256, SMEM_GEMM>>>(
        ath, atl, woh, wol, out, HIDDEN);
}